// round 9
// baseline (speedup 1.0000x reference)
#include <cuda_runtime.h>

// GLCM entropy per image, pooled over 4 angles (d=1, wraparound), 16 levels.
// x: [N_IMG, 512, 512] f32 in [0,1). out: each (b,c) slice filled with its scalar entropy.

#define HH 512
#define WW 512
#define RPB 16         // rows per histogram block
#define TPB 256
#define MAXIMG 256

__device__ unsigned int g_counts[MAXIMG * 256];
__device__ float g_ent[MAXIMG];

__global__ void zero_counts_kernel(int n) {
    int i = blockIdx.x * blockDim.x + threadIdx.x;
    if (i < n) g_counts[i] = 0u;
}

__global__ __launch_bounds__(TPB) void hist_kernel(const float* __restrict__ x) {
    const int img = blockIdx.y;
    const int r0 = blockIdx.x * RPB;
    const float4* base4 = (const float4*)(x + (size_t)img * (HH * WW));

    // Quantized tile as packed words: 128 uint32 per row (4 px/word), rows r0-1..r0+RPB-1.
    __shared__ unsigned int tile32[(RPB + 1) * (WW / 4)];
    // Per-warp histograms as BYTE counters: 256 bins -> 64 packed words per warp.
    // Safe: per-warp per-bin count ~Binomial(4096, 1/256) for uniform input, << 255.
    __shared__ unsigned int hist[8 * 64];

    const int tid = threadIdx.x;
    const int W4 = WW / 4;                           // 128 words per row

    for (int k = tid; k < 8 * 64; k += TPB) hist[k] = 0u;

    // Load + quantize, pack 4 bytes -> 1 word STS.
    for (int k = tid; k < (RPB + 1) * W4; k += TPB) {
        int rr = k >> 7;                             // k / 128
        int c4 = k & (W4 - 1);
        int gr = (r0 - 1 + rr + HH) & (HH - 1);
        float4 v = base4[gr * W4 + c4];
        unsigned int b0 = (unsigned int)(int)(v.x * 15.0f);   // trunc == (x*15).astype(int)
        unsigned int b1 = (unsigned int)(int)(v.y * 15.0f);
        unsigned int b2 = (unsigned int)(int)(v.z * 15.0f);
        unsigned int b3 = (unsigned int)(int)(v.w * 15.0f);
        tile32[k] = b0 | (b1 << 8) | (b2 << 16) | (b3 << 24);
    }
    __syncthreads();

    unsigned int* wh = hist + ((tid >> 5) << 6);     // this warp's 64-word histogram

    // Each thread: one aligned word = 4 pixels.
    // Pixel pairs with: left (0deg), up-right (45), up (90), up-left (135).
    for (int w = tid; w < RPB * W4; w += TPB) {
        int rr = (w >> 7) + 1;                       // tile rows 1..RPB
        int c4 = w & (W4 - 1);
        int row = rr * W4;
        int up  = row - W4;
        int c4m = (c4 - 1) & (W4 - 1);
        int c4p = (c4 + 1) & (W4 - 1);

        unsigned int cw  = tile32[row + c4];
        unsigned int uw  = tile32[up + c4];
        unsigned int lb  = tile32[row + c4m] >> 24;  // left neighbor of pixel 0
        unsigned int ulb = tile32[up + c4m] >> 24;   // up-left of pixel 0
        unsigned int urb = tile32[up + c4p] & 0xFFu; // up-right of pixel 3

        unsigned int cl = (cw << 8) | lb;            // byte k = left  neighbor of pixel k
        unsigned int ul = (uw << 8) | ulb;           // byte k = up-left
        unsigned int ur = (uw >> 8) | (urb << 24);   // byte k = up-right
                                                     // byte k of uw = up neighbor

        // Per-byte bin indices: bin = (q<<4) | s.
        unsigned int qb  = (cw << 4) & 0xF0F0F0F0u;
        unsigned int bb0 = qb | cl;
        unsigned int bb1 = qb | ur;
        unsigned int bb2 = qb | uw;
        unsigned int bb3 = qb | ul;

        #pragma unroll
        for (int k = 0; k < 4; k++) {
            int sh = k * 8;
            unsigned int e0 = (bb0 >> sh) & 255u;
            unsigned int e1 = (bb1 >> sh) & 255u;
            unsigned int e2 = (bb2 >> sh) & 255u;
            unsigned int e3 = (bb3 >> sh) & 255u;
            // packed word index (bin>>2) and byte-lane addend 1<<((bin&3)*8)
            unsigned int w0 = e0 >> 2, w1 = e1 >> 2, w2 = e2 >> 2, w3 = e3 >> 2;
            unsigned int a0 = 1u << ((e0 & 3u) << 3);
            unsigned int a1 = 1u << ((e1 & 3u) << 3);
            unsigned int a2 = 1u << ((e2 & 3u) << 3);
            unsigned int a3 = 1u << ((e3 & 3u) << 3);

            // Dedup on word index (all 4 words lie in q*4+{0..3}); merge addends.
            bool m10 = (w1 == w0);                 a0 += m10 ? a1 : 0u;
            bool m20 = (w2 == w0);
            bool m21 = (w2 == w1) && !m20;         a0 += m20 ? a2 : 0u;
                                                   a1 += m21 ? a2 : 0u;
            bool m30 = (w3 == w0);
            bool m31 = (w3 == w1) && !m30;
            bool m32 = (w3 == w2) && !m30 && !m31; a0 += m30 ? a3 : 0u;
                                                   a1 += m31 ? a3 : 0u;
                                                   a2 += m32 ? a3 : 0u;

            atomicAdd(&wh[w0], a0);
            if (!m10)         atomicAdd(&wh[w1], a1);
            if (!m20 && !m21) atomicAdd(&wh[w2], a2);
            if (!m30 && !m31 && !m32) atomicAdd(&wh[w3], a3);
        }
    }
    __syncthreads();

    // Merge: thread tid = bin. Byte (tid&3) of packed word (tid>>2) across 8 warps.
    unsigned int s = 0;
    int word = tid >> 2;
    int bsh  = (tid & 3) << 3;
    #pragma unroll
    for (int w = 0; w < 8; w++) s += (hist[w * 64 + word] >> bsh) & 255u;
    atomicAdd(&g_counts[img * 256 + tid], s);
}

__global__ __launch_bounds__(256) void entropy_kernel() {
    const int img = blockIdx.x;
    const int tid = threadIdx.x;
    __shared__ float warp_red[8];

    float c = (float)g_counts[img * 256 + tid];
    const float inv = 1.0f / (4.0f * HH * WW);       // counts.sum() == 4*H*W exactly
    float p = c * inv;
    float v = p * __logf(p + 1e-10f);

    #pragma unroll
    for (int s = 16; s > 0; s >>= 1) v += __shfl_xor_sync(0xFFFFFFFFu, v, s);
    if ((tid & 31) == 0) warp_red[tid >> 5] = v;
    __syncthreads();
    if (tid < 8) {
        float t = warp_red[tid];
        #pragma unroll
        for (int s = 4; s > 0; s >>= 1) t += __shfl_xor_sync(0xFFu, t, s);
        if (tid == 0) g_ent[img] = -t;
    }
}

__global__ __launch_bounds__(256) void fill_kernel(float4* __restrict__ out, int n4) {
    // Best measured config: 4 float4 per thread, lane-contiguous, streaming stores.
    int base = blockIdx.x * (256 * 4) + threadIdx.x;
    #pragma unroll
    for (int i = 0; i < 4; i++) {
        int idx = base + i * 256;
        if (idx < n4) {
            float v = g_ent[idx >> 16];              // 2^16 float4 per image
            __stcs(&out[idx], make_float4(v, v, v, v));
        }
    }
}

extern "C" void kernel_launch(void* const* d_in, const int* in_sizes, int n_in,
                              void* d_out, int out_size) {
    const float* x = (const float*)d_in[0];
    int n_img = in_sizes[0] / (HH * WW);             // 8*16 = 128

    int nc = n_img * 256;
    zero_counts_kernel<<<(nc + 255) / 256, 256>>>(nc);

    dim3 hgrid(HH / RPB, n_img);
    hist_kernel<<<hgrid, TPB>>>(x);

    entropy_kernel<<<n_img, 256>>>();

    int n4 = out_size / 4;
    fill_kernel<<<(n4 + 256 * 4 - 1) / (256 * 4), 256>>>((float4*)d_out, n4);
}

// round 11
// speedup vs baseline: 1.5133x; 1.5133x over previous
#include <cuda_runtime.h>

// GLCM entropy per image, pooled over 4 angles (d=1, wraparound), 16 levels.
// x: [N_IMG, 512, 512] f32 in [0,1). out: each (b,c) slice filled with its scalar entropy.

#define HH 512
#define WW 512
#define RPB 16         // rows per histogram block
#define TPB 256
#define MAXIMG 256

__device__ unsigned int g_counts[MAXIMG * 256];
__device__ float g_ent[MAXIMG];

__global__ void zero_counts_kernel(int n) {
    int i = blockIdx.x * blockDim.x + threadIdx.x;
    if (i < n) g_counts[i] = 0u;
}

__global__ __launch_bounds__(TPB) void hist_kernel(const float* __restrict__ x) {
    const int img = blockIdx.y;
    const int r0 = blockIdx.x * RPB;
    const float4* base4 = (const float4*)(x + (size_t)img * (HH * WW));

    // Quantized tile as packed words: 128 uint32 per row (4 px/word), rows r0-1..r0+RPB-1.
    __shared__ unsigned int tile32[(RPB + 1) * (WW / 4)];
    // Lane-column histogram: hist[bin*32 + lane]. Every lane only ever touches
    // its own bank column -> zero bank conflicts, zero intra-warp same-address
    // replays, for ANY input. Atomics only arbitrate across the 8 warps.
    __shared__ unsigned int hist[256 * 32];          // 32 KB

    const int tid = threadIdx.x;
    const int lane = tid & 31;
    const int W4 = WW / 4;                           // 128 words per row

    for (int k = tid; k < 256 * 32; k += TPB) hist[k] = 0u;

    // Load + quantize, pack 4 bytes -> 1 word STS.
    for (int k = tid; k < (RPB + 1) * W4; k += TPB) {
        int rr = k >> 7;                             // k / 128
        int c4 = k & (W4 - 1);
        int gr = (r0 - 1 + rr + HH) & (HH - 1);
        float4 v = base4[gr * W4 + c4];
        unsigned int b0 = (unsigned int)(int)(v.x * 15.0f);   // trunc == (x*15).astype(int)
        unsigned int b1 = (unsigned int)(int)(v.y * 15.0f);
        unsigned int b2 = (unsigned int)(int)(v.z * 15.0f);
        unsigned int b3 = (unsigned int)(int)(v.w * 15.0f);
        tile32[k] = b0 | (b1 << 8) | (b2 << 16) | (b3 << 24);
    }
    __syncthreads();

    unsigned int* wh = hist + lane;                  // this lane's bank column

    // Each thread: one aligned word = 4 pixels.
    // Pixel pairs with: left (0deg), up-right (45), up (90), up-left (135).
    for (int w = tid; w < RPB * W4; w += TPB) {
        int rr = (w >> 7) + 1;                       // tile rows 1..RPB
        int c4 = w & (W4 - 1);
        int row = rr * W4;
        int up  = row - W4;
        int c4m = (c4 - 1) & (W4 - 1);
        int c4p = (c4 + 1) & (W4 - 1);

        unsigned int cw  = tile32[row + c4];
        unsigned int uw  = tile32[up + c4];
        unsigned int lb  = tile32[row + c4m] >> 24;  // left neighbor of pixel 0
        unsigned int ulb = tile32[up + c4m] >> 24;   // up-left of pixel 0
        unsigned int urb = tile32[up + c4p] & 0xFFu; // up-right of pixel 3

        unsigned int cl = (cw << 8) | lb;            // byte k = left  neighbor of pixel k
        unsigned int ul = (uw << 8) | ulb;           // byte k = up-left
        unsigned int ur = (uw >> 8) | (urb << 24);   // byte k = up-right
                                                     // byte k of uw = up neighbor

        // Per-byte bin indices: bin = (q<<4) | s, 4 pixels at a time per angle.
        unsigned int qb   = (cw << 4) & 0xF0F0F0F0u;
        unsigned int b0   = qb | cl;
        unsigned int b45  = qb | ur;
        unsigned int b90  = qb | uw;
        unsigned int b135 = qb | ul;

        #pragma unroll
        for (int k = 0; k < 4; k++) {
            int sh = k * 8;
            atomicAdd(&wh[(((b0   >> sh) & 255u) << 5)], 1u);
            atomicAdd(&wh[(((b45  >> sh) & 255u) << 5)], 1u);
            atomicAdd(&wh[(((b90  >> sh) & 255u) << 5)], 1u);
            atomicAdd(&wh[(((b135 >> sh) & 255u) << 5)], 1u);
        }
    }
    __syncthreads();

    // Merge: thread tid = bin; sum its 32 lane columns with rotation -> conflict-free.
    unsigned int s = 0;
    const unsigned int* hrow = hist + (tid << 5);
    #pragma unroll
    for (int i = 0; i < 32; i++) {
        s += hrow[(lane + i) & 31];
    }
    atomicAdd(&g_counts[img * 256 + tid], s);
}

__global__ __launch_bounds__(256) void entropy_kernel() {
    const int img = blockIdx.x;
    const int tid = threadIdx.x;
    __shared__ float warp_red[8];

    float c = (float)g_counts[img * 256 + tid];
    const float inv = 1.0f / (4.0f * HH * WW);       // counts.sum() == 4*H*W exactly
    float p = c * inv;
    float v = p * __logf(p + 1e-10f);

    #pragma unroll
    for (int s = 16; s > 0; s >>= 1) v += __shfl_xor_sync(0xFFFFFFFFu, v, s);
    if ((tid & 31) == 0) warp_red[tid >> 5] = v;
    __syncthreads();
    if (tid < 8) {
        float t = warp_red[tid];
        #pragma unroll
        for (int s = 4; s > 0; s >>= 1) t += __shfl_xor_sync(0xFFu, t, s);
        if (tid == 0) g_ent[img] = -t;
    }
}

__global__ __launch_bounds__(256) void fill_kernel(float4* __restrict__ out, int n4) {
    // Best measured config: 4 float4 per thread, lane-contiguous, streaming stores.
    int base = blockIdx.x * (256 * 4) + threadIdx.x;
    #pragma unroll
    for (int i = 0; i < 4; i++) {
        int idx = base + i * 256;
        if (idx < n4) {
            float v = g_ent[idx >> 16];              // 2^16 float4 per image
            __stcs(&out[idx], make_float4(v, v, v, v));
        }
    }
}

extern "C" void kernel_launch(void* const* d_in, const int* in_sizes, int n_in,
                              void* d_out, int out_size) {
    const float* x = (const float*)d_in[0];
    int n_img = in_sizes[0] / (HH * WW);             // 8*16 = 128

    int nc = n_img * 256;
    zero_counts_kernel<<<(nc + 255) / 256, 256>>>(nc);

    dim3 hgrid(HH / RPB, n_img);
    hist_kernel<<<hgrid, TPB>>>(x);

    entropy_kernel<<<n_img, 256>>>();

    int n4 = out_size / 4;
    fill_kernel<<<(n4 + 256 * 4 - 1) / (256 * 4), 256>>>((float4*)d_out, n4);
}